// round 5
// baseline (speedup 1.0000x reference)
#include <cuda_runtime.h>
#include <cstdint>

// Problem constants
#define S_LEN   512
#define BATCH   64
#define HID     512
#define GCOLS   2048              // 4*H
#define NCTA    128               // 2048 gate cols / 16 per CTA (4 hc x 4 gates)
#define NTHR    256               // 4 K-quarters x (32 row-pairs x 2 col-groups)
#define RED_STRIDE 18             // ull stride per reduction slot (16B-aligned, low conflict)

typedef unsigned long long ull;

// ---- persistent device state (allocation-free rule: __device__ globals) ----
__device__ __align__(128) float g_h0[2][BATCH * HID];
__device__ __align__(128) float g_h1[2][BATCH * HID];
__device__ __align__(128) float g_c0[BATCH * HID];
__device__ __align__(128) float g_c1[BATCH * HID];
// packed weights: [layer][cta][kp(512)][cg(2)][hh(2)][g(4)][e(2)]  (16384 floats/cta/layer)
__device__ __align__(128) float g_wpack[2][NCTA * 16384];

// ---------------- cp.async helpers ----------------
__device__ __forceinline__ void cpa16(uint32_t dst, const float* src) {
    asm volatile("cp.async.cg.shared.global [%0], [%1], 16;\n" :: "r"(dst), "l"(src));
}
__device__ __forceinline__ void cp_commit() { asm volatile("cp.async.commit_group;\n" ::: "memory"); }
__device__ __forceinline__ void cp_wait1()  { asm volatile("cp.async.wait_group 1;\n" ::: "memory"); }
__device__ __forceinline__ void cp_wait0()  { asm volatile("cp.async.wait_group 0;\n" ::: "memory"); }

// ---------------- packed fp32x2 helpers ----------------
__device__ __forceinline__ ull ffma2(ull x, ull w, ull acc) {
    asm("fma.rn.f32x2 %0, %1, %2, %0;" : "+l"(acc) : "l"(x), "l"(w));
    return acc;
}
__device__ __forceinline__ ull add2(ull a, ull b) {
    ull r; asm("add.rn.f32x2 %0, %1, %2;" : "=l"(r) : "l"(a), "l"(b)); return r;
}
__device__ __forceinline__ float sum2(ull v) {
    float lo, hi; asm("mov.b64 {%0, %1}, %2;" : "=f"(lo), "=f"(hi) : "l"(v));
    return lo + hi;
}
__device__ __forceinline__ float sigmoidf_(float x) { return 1.0f / (1.0f + __expf(-x)); }

// ---- K-quarter GEMM: accA/accB[hh*4+g] += rows(rA,rB) x W(8 cols), K=256 ----
// rowA/rowB: global ptrs to this quarter's 256 K-values of the two rows.
// wq: smem base for this (layer, quarter, cg): per iter i (4 k = 2 kp) -> 64 floats.
__device__ __forceinline__ void mma_quarter(const float* __restrict__ rowA,
                                            const float* __restrict__ rowB,
                                            const float* __restrict__ wq,
                                            ull accA[8], ull accB[8]) {
    const ulonglong2* pA = (const ulonglong2*)rowA;
    const ulonglong2* pB = (const ulonglong2*)rowB;
#pragma unroll 4
    for (int i = 0; i < 64; i++) {
        ulonglong2 a2 = pA[i];                 // rA: k-quad (LDG.128)
        ulonglong2 b2 = pB[i];                 // rB: k-quad
        const ulonglong2* we = (const ulonglong2*)(wq + i * 64);        // kp even
        const ulonglong2* wo = (const ulonglong2*)(wq + i * 64 + 32);   // kp odd
#pragma unroll
        for (int j = 0; j < 4; j++) {          // j -> (hh, g-pair): acc 2j, 2j+1
            ulonglong2 w = we[j];              // uniform per warp -> LDS broadcast
            accA[2*j]   = ffma2(a2.x, w.x, accA[2*j]);
            accA[2*j+1] = ffma2(a2.x, w.y, accA[2*j+1]);
            accB[2*j]   = ffma2(b2.x, w.x, accB[2*j]);
            accB[2*j+1] = ffma2(b2.x, w.y, accB[2*j+1]);
        }
#pragma unroll
        for (int j = 0; j < 4; j++) {
            ulonglong2 w = wo[j];
            accA[2*j]   = ffma2(a2.y, w.x, accA[2*j]);
            accA[2*j+1] = ffma2(a2.y, w.y, accA[2*j+1]);
            accB[2*j]   = ffma2(b2.y, w.x, accB[2*j]);
            accB[2*j+1] = ffma2(b2.y, w.y, accB[2*j+1]);
        }
    }
}

// ---- epilogue (quarter 0 only): fold partials, add 2*b, cell update, write ----
__device__ __forceinline__ void do_epilogue(ull accA[8], ull accB[8], const ull* red,
                                            int t64, const float* __restrict__ bias,
                                            float* __restrict__ hdst,
                                            float* __restrict__ cst,
                                            float* __restrict__ odst,
                                            int rA, int rB, int hcbase) {
#pragma unroll
    for (int s = 0; s < 3; s++) {
        const ull* slot = red + (size_t)(s * 64 + t64) * RED_STRIDE;
#pragma unroll
        for (int j = 0; j < 8; j++) {
            accA[j] = add2(accA[j], slot[j]);
            accB[j] = add2(accB[j], slot[8 + j]);
        }
    }
#pragma unroll
    for (int hh = 0; hh < 2; hh++) {
        int hc = hcbase + hh;
        float b2f[4];
#pragma unroll
        for (int g = 0; g < 4; g++) b2f[g] = 2.0f * bias[g * HID + hc];

        // gates order per reference split: f, i1, i2, o
        float fA  = sigmoidf_(sum2(accA[hh*4+0]) + b2f[0]);
        float i1A = sigmoidf_(sum2(accA[hh*4+1]) + b2f[1]);
        float i2A = tanhf   (sum2(accA[hh*4+2]) + b2f[2]);
        float oA  = sigmoidf_(sum2(accA[hh*4+3]) + b2f[3]);
        float fB  = sigmoidf_(sum2(accB[hh*4+0]) + b2f[0]);
        float i1B = sigmoidf_(sum2(accB[hh*4+1]) + b2f[1]);
        float i2B = tanhf   (sum2(accB[hh*4+2]) + b2f[2]);
        float oB  = sigmoidf_(sum2(accB[hh*4+3]) + b2f[3]);

        float cA = cst[rA * HID + hc], cB = cst[rB * HID + hc];
        cA = fA * cA + i1A * i2A;
        cB = fB * cB + i1B * i2B;
        cst[rA * HID + hc] = cA;  cst[rB * HID + hc] = cB;
        float hA = oA * tanhf(cA);
        float hB = oB * tanhf(cB);
        hdst[rA * HID + hc] = hA;  hdst[rB * HID + hc] = hB;
        if (odst) { odst[rA * HID + hc] = hA;  odst[rB * HID + hc] = hB; }
    }
}

// ---- one-time per replay: repack weights: [cta][kp][cg][hh][g][e] ----
__global__ void pack_kernel(const float* __restrict__ Wx0, const float* __restrict__ Wh0,
                            const float* __restrict__ Wx1, const float* __restrict__ Wh1) {
    int cta = blockIdx.x;
    for (int idx = threadIdx.x; idx < 16384; idx += blockDim.x) {
        int e  = idx & 1;
        int g  = (idx >> 1) & 3;
        int hh = (idx >> 3) & 1;
        int cg = (idx >> 4) & 1;
        int kp = idx >> 5;
        int k   = kp * 2 + e;
        int col = g * HID + cta * 4 + cg * 2 + hh;
        g_wpack[0][cta * 16384 + idx] =
            (k < HID) ? Wx0[k * GCOLS + col] : Wh0[(k - HID) * GCOLS + col];
        g_wpack[1][cta * 16384 + idx] =
            (k < HID) ? Wx1[k * GCOLS + col] : Wh1[(k - HID) * GCOLS + col];
    }
}

__global__ void init_kernel() {
    int idx = blockIdx.x * blockDim.x + threadIdx.x;
    if (idx < BATCH * HID) {
        g_h0[0][idx] = 0.f; g_h0[1][idx] = 0.f;
        g_h1[0][idx] = 0.f; g_h1[1][idx] = 0.f;
        g_c0[idx] = 0.f;    g_c1[idx] = 0.f;
    }
}

// ---- skewed step: launch k does layer0(step k) and layer1(step k-1) ----
__global__ __launch_bounds__(NTHR, 1)
void step_kernel(const float* __restrict__ x,
                 const float* __restrict__ b0, const float* __restrict__ b1,
                 float* __restrict__ out, int k) {
    extern __shared__ float sm[];
    float* w_sm = sm;                                  // 32768 floats (128KB): both layers
    ull* redA = (ull*)(sm + 32768);                    // 3*64*RED_STRIDE ull
    ull* redB = redA + 3 * 64 * RED_STRIDE;

    const int tid = threadIdx.x;
    const int cta = blockIdx.x;
    const int q   = tid >> 6;          // K quarter 0..3
    const int t64 = tid & 63;
    const int r   = tid & 31;          // row pair
    const int cg  = (tid >> 5) & 1;    // col group (uniform per warp)
    const int rA = r, rB = r + 32;
    const int hcbase = cta * 4 + cg * 2;
    const int p = k & 1, pq = p ^ 1;
    const int koff = (q & 1) * 256;    // K offset within the selected source

    // ---- stage packed weights into smem (layer0 first, then layer1) ----
    {
        const float* wg0 = g_wpack[0] + cta * 16384;
        const float* wg1 = g_wpack[1] + cta * 16384;
#pragma unroll
        for (int ii = 0; ii < 16; ii++) {
            int off = (ii * NTHR + tid) * 4;
            cpa16((uint32_t)__cvta_generic_to_shared(w_sm + off), wg0 + off);
        }
        cp_commit();
#pragma unroll
        for (int ii = 0; ii < 16; ii++) {
            int off = (ii * NTHR + tid) * 4;
            cpa16((uint32_t)__cvta_generic_to_shared(w_sm + 16384 + off), wg1 + off);
        }
        cp_commit();
    }
    cp_wait1();            // layer0 weights landed
    __syncthreads();

    const float* wq_me = w_sm + q * 4096 + cg * 16;   // my (quarter, cg) base, layer0

    // ---- phase A: layer 0, step k ----
    ull accA[8], accB[8];
    if (k < S_LEN) {
#pragma unroll
        for (int j = 0; j < 8; j++) { accA[j] = 0ull; accB[j] = 0ull; }
        const float* src = (q < 2) ? (x + (size_t)k * BATCH * HID) : g_h0[p];
        mma_quarter(src + rA * HID + koff, src + rB * HID + koff, wq_me, accA, accB);
        if (q != 0) {
            ull* slot = redA + (size_t)((q - 1) * 64 + t64) * RED_STRIDE;
#pragma unroll
            for (int j = 0; j < 8; j++) { slot[j] = accA[j]; slot[8 + j] = accB[j]; }
        }
    }
    cp_wait0();            // layer1 weights landed (overlapped with phase A)
    __syncthreads();

    if (k < S_LEN && q == 0) {
        do_epilogue(accA, accB, redA, t64, b0, g_h0[pq], g_c0, nullptr, rA, rB, hcbase);
    }

    // ---- phase B: layer 1, step k-1 (reads h0 written by PREVIOUS launch) ----
    if (k > 0) {
#pragma unroll
        for (int j = 0; j < 8; j++) { accA[j] = 0ull; accB[j] = 0ull; }
        const float* src = (q < 2) ? g_h0[p] : g_h1[p];
        mma_quarter(src + rA * HID + koff, src + rB * HID + koff,
                    wq_me + 16384, accA, accB);
        if (q != 0) {
            ull* slot = redB + (size_t)((q - 1) * 64 + t64) * RED_STRIDE;
#pragma unroll
            for (int j = 0; j < 8; j++) { slot[j] = accA[j]; slot[8 + j] = accB[j]; }
        }
    }
    __syncthreads();

    if (k > 0 && q == 0) {
        do_epilogue(accA, accB, redB, t64, b1, g_h1[pq], g_c1,
                    out + (size_t)(k - 1) * BATCH * HID, rA, rB, hcbase);
    }
}

extern "C" void kernel_launch(void* const* d_in, const int* in_sizes, int n_in,
                              void* d_out, int out_size) {
    const float* x   = (const float*)d_in[0];
    const float* Wx0 = (const float*)d_in[1];
    const float* Wh0 = (const float*)d_in[2];
    const float* b0  = (const float*)d_in[3];
    const float* Wx1 = (const float*)d_in[4];
    const float* Wh1 = (const float*)d_in[5];
    const float* b1  = (const float*)d_in[6];
    float* out = (float*)d_out;

    size_t smem = 32768 * sizeof(float) + 2 * 3 * 64 * RED_STRIDE * sizeof(ull); // ~182KB
    static int attr_done = 0;
    if (!attr_done) {
        cudaFuncSetAttribute(step_kernel,
                             cudaFuncAttributeMaxDynamicSharedMemorySize, (int)smem);
        attr_done = 1;
    }

    pack_kernel<<<NCTA, 256>>>(Wx0, Wh0, Wx1, Wh1);
    init_kernel<<<(BATCH * HID + 255) / 256, 256>>>();
    for (int k = 0; k <= S_LEN; k++) {
        step_kernel<<<NCTA, NTHR, smem>>>(x, b0, b1, out, k);
    }
}

// round 6
// speedup vs baseline: 1.5298x; 1.5298x over previous
#include <cuda_runtime.h>
#include <cstdint>

// Problem constants
#define S_LEN   512
#define BATCH   64
#define HID     512
#define GCOLS   2048
#define NCTA    128               // 16 gate cols per CTA (8 h-cols... 4 hc x 4 gates)
#define NTHR    256               // 4 K-quarters x 2 warps (hl) x 32 lanes (rows)
#define RED_STRIDE 18             // ull stride per reduction slot (16B-aligned)

#define KP_CHUNK 16               // kp (k-pairs) per chunk = 32 k
#define NCHUNK   8                // chunks per quarter per phase (256 k / 32)
#define T_F2     (KP_CHUNK * 65)  // 1040 float2 per T buffer (pad 65 rows)
#define W_FL     (KP_CHUNK * 32)  // 512 floats per weight chunk

// smem layout (bytes)
#define SM_T_BYTES   (4 * 3 * T_F2 * 8)            // 99840
#define SM_W_BYTES   (4 * 3 * W_FL * 4)            // 24576
#define SM_RED_ULL   (3 * 64 * RED_STRIDE)         // 3456 ull per red buffer
#define SM_TOTAL     (SM_T_BYTES + SM_W_BYTES + 2 * SM_RED_ULL * 8)   // ~180KB

typedef unsigned long long ull;

// ---- persistent device state (allocation-free rule: __device__ globals) ----
__device__ __align__(128) float g_h0[2][BATCH * HID];
__device__ __align__(128) float g_h1[2][BATCH * HID];
__device__ __align__(128) float g_c0[BATCH * HID];
__device__ __align__(128) float g_c1[BATCH * HID];
// packed weights: [layer][cta][kp(512)][cg(2)][hh(2)][g(4)][e(2)]
__device__ __align__(128) float g_wpack[2][NCTA * 16384];

// ---------------- helpers ----------------
__device__ __forceinline__ void cpa16(uint32_t dst, const float* src) {
    asm volatile("cp.async.cg.shared.global [%0], [%1], 16;\n" :: "r"(dst), "l"(src));
}
__device__ __forceinline__ void cp_commit() { asm volatile("cp.async.commit_group;\n" ::: "memory"); }
__device__ __forceinline__ void cp_wait1()  { asm volatile("cp.async.wait_group 1;\n" ::: "memory"); }
__device__ __forceinline__ void cp_wait0()  { asm volatile("cp.async.wait_group 0;\n" ::: "memory"); }
__device__ __forceinline__ void bar_sync(int id, int cnt) {
    asm volatile("bar.sync %0, %1;" :: "r"(id), "r"(cnt) : "memory");
}
__device__ __forceinline__ ull ffma2(ull x, ull w, ull acc) {
    asm("fma.rn.f32x2 %0, %1, %2, %0;" : "+l"(acc) : "l"(x), "l"(w));
    return acc;
}
__device__ __forceinline__ ull add2(ull a, ull b) {
    ull r; asm("add.rn.f32x2 %0, %1, %2;" : "=l"(r) : "l"(a), "l"(b)); return r;
}
__device__ __forceinline__ float sum2(ull v) {
    float lo, hi; asm("mov.b64 {%0, %1}, %2;" : "=f"(lo), "=f"(hi) : "l"(v));
    return lo + hi;
}
__device__ __forceinline__ float sigmoidf_(float x) { return 1.0f / (1.0f + __expf(-x)); }

// ---- stage one chunk: weights via cp.async, inputs transposed via LDG+STS ----
// T layout: Tbuf[kp][row] as float2 (pair k=2kp,2kp+1), row-stride 65.
__device__ __forceinline__ void stage(const float* __restrict__ src,   // rows [64][512], k-offset applied
                                      const float* __restrict__ wsrc,  // 512 floats contiguous
                                      float2* __restrict__ Tbuf, float* __restrict__ Wbuf,
                                      int tid64) {
    cpa16((uint32_t)__cvta_generic_to_shared(Wbuf + tid64 * 8),     wsrc + tid64 * 8);
    cpa16((uint32_t)__cvta_generic_to_shared(Wbuf + tid64 * 8 + 4), wsrc + tid64 * 8 + 4);
    float2 v[16];
#pragma unroll
    for (int j = 0; j < 16; j++) {
        int e = j * 64 + tid64;
        int kp = e & 15, row = e >> 4;
        v[j] = *(const float2*)(src + row * HID + kp * 2);   // coalesced LDG.64
    }
#pragma unroll
    for (int j = 0; j < 16; j++) {
        int e = j * 64 + tid64;
        int kp = e & 15, row = e >> 4;
        Tbuf[kp * 65 + row] = v[j];                          // transposed STS.64
    }
    cp_commit();
}

// ---- compute one chunk: 16 kp x (2 rows x 2 hh x 4 gates) ----
__device__ __forceinline__ void mma_chunk(const float2* __restrict__ T,
                                          const float* __restrict__ W,
                                          int r, int hl, ull aA[8], ull aB[8]) {
#pragma unroll 4
    for (int kp = 0; kp < KP_CHUNK; kp++) {
        ull a = *(const ull*)(T + kp * 65 + r);        // conflict-free LDS.64
        ull b = *(const ull*)(T + kp * 65 + r + 32);
        const ulonglong2* wp = (const ulonglong2*)W + kp * 8 + hl * 4;  // uniform -> broadcast
        ulonglong2 w01 = wp[0], w23 = wp[1];           // hh0: gates 0,1 | 2,3
        ulonglong2 w45 = wp[2], w67 = wp[3];           // hh1
        aA[0] = ffma2(a, w01.x, aA[0]);  aA[1] = ffma2(a, w01.y, aA[1]);
        aA[2] = ffma2(a, w23.x, aA[2]);  aA[3] = ffma2(a, w23.y, aA[3]);
        aA[4] = ffma2(a, w45.x, aA[4]);  aA[5] = ffma2(a, w45.y, aA[5]);
        aA[6] = ffma2(a, w67.x, aA[6]);  aA[7] = ffma2(a, w67.y, aA[7]);
        aB[0] = ffma2(b, w01.x, aB[0]);  aB[1] = ffma2(b, w01.y, aB[1]);
        aB[2] = ffma2(b, w23.x, aB[2]);  aB[3] = ffma2(b, w23.y, aB[3]);
        aB[4] = ffma2(b, w45.x, aB[4]);  aB[5] = ffma2(b, w45.y, aB[5]);
        aB[6] = ffma2(b, w67.x, aB[6]);  aB[7] = ffma2(b, w67.y, aB[7]);
    }
}

// ---- per-quarter pipeline: 8 chunks, triple-buffered, named-barrier synced ----
__device__ __forceinline__ void run_pipe(const float* __restrict__ src,   // +quarter k-offset
                                         const float* __restrict__ wsrc,  // +quarter offset
                                         float2* __restrict__ Tq, float* __restrict__ Wq,
                                         int tid64, int r, int hl, int barid,
                                         ull aA[8], ull aB[8]) {
    stage(src, wsrc, Tq, Wq, tid64);
#pragma unroll 1
    for (int i = 0; i < NCHUNK; i++) {
        if (i < NCHUNK - 1) {
            int ib = (i + 1) % 3;
            stage(src + (i + 1) * 32, wsrc + (i + 1) * W_FL,
                  Tq + ib * T_F2, Wq + ib * W_FL, tid64);
            cp_wait1();
        } else {
            cp_wait0();
        }
        bar_sync(barid, 64);
        mma_chunk(Tq + (i % 3) * T_F2, Wq + (i % 3) * W_FL, r, hl, aA, aB);
    }
}

// ---- epilogue (quarter 0): fold partials, add 2*b, cell update, write ----
__device__ __forceinline__ void do_epilogue(ull accA[8], ull accB[8], const ull* red,
                                            int t64, const float* __restrict__ bias,
                                            float* __restrict__ hdst,
                                            float* __restrict__ cst,
                                            float* __restrict__ odst,
                                            int rA, int rB, int hcbase) {
#pragma unroll
    for (int s = 0; s < 3; s++) {
        const ull* slot = red + (size_t)(s * 64 + t64) * RED_STRIDE;
#pragma unroll
        for (int j = 0; j < 8; j++) {
            accA[j] = add2(accA[j], slot[j]);
            accB[j] = add2(accB[j], slot[8 + j]);
        }
    }
#pragma unroll
    for (int hh = 0; hh < 2; hh++) {
        int hc = hcbase + hh;
        float b2f[4];
#pragma unroll
        for (int g = 0; g < 4; g++) b2f[g] = 2.0f * bias[g * HID + hc];

        float fA  = sigmoidf_(sum2(accA[hh*4+0]) + b2f[0]);
        float i1A = sigmoidf_(sum2(accA[hh*4+1]) + b2f[1]);
        float i2A = tanhf   (sum2(accA[hh*4+2]) + b2f[2]);
        float oA  = sigmoidf_(sum2(accA[hh*4+3]) + b2f[3]);
        float fB  = sigmoidf_(sum2(accB[hh*4+0]) + b2f[0]);
        float i1B = sigmoidf_(sum2(accB[hh*4+1]) + b2f[1]);
        float i2B = tanhf   (sum2(accB[hh*4+2]) + b2f[2]);
        float oB  = sigmoidf_(sum2(accB[hh*4+3]) + b2f[3]);

        float cA = cst[rA * HID + hc], cB = cst[rB * HID + hc];
        cA = fA * cA + i1A * i2A;
        cB = fB * cB + i1B * i2B;
        cst[rA * HID + hc] = cA;  cst[rB * HID + hc] = cB;
        float hA = oA * tanhf(cA);
        float hB = oB * tanhf(cB);
        hdst[rA * HID + hc] = hA;  hdst[rB * HID + hc] = hB;
        if (odst) { odst[rA * HID + hc] = hA;  odst[rB * HID + hc] = hB; }
    }
}

// ---- one-time per replay: repack weights [cta][kp][cg][hh][g][e] ----
__global__ void pack_kernel(const float* __restrict__ Wx0, const float* __restrict__ Wh0,
                            const float* __restrict__ Wx1, const float* __restrict__ Wh1) {
    int cta = blockIdx.x;
    for (int idx = threadIdx.x; idx < 16384; idx += blockDim.x) {
        int e  = idx & 1;
        int g  = (idx >> 1) & 3;
        int hh = (idx >> 3) & 1;
        int cg = (idx >> 4) & 1;
        int kp = idx >> 5;
        int k   = kp * 2 + e;
        int col = g * HID + cta * 4 + cg * 2 + hh;
        g_wpack[0][cta * 16384 + idx] =
            (k < HID) ? Wx0[k * GCOLS + col] : Wh0[(k - HID) * GCOLS + col];
        g_wpack[1][cta * 16384 + idx] =
            (k < HID) ? Wx1[k * GCOLS + col] : Wh1[(k - HID) * GCOLS + col];
    }
}

__global__ void init_kernel() {
    int idx = blockIdx.x * blockDim.x + threadIdx.x;
    if (idx < BATCH * HID) {
        g_h0[0][idx] = 0.f; g_h0[1][idx] = 0.f;
        g_h1[0][idx] = 0.f; g_h1[1][idx] = 0.f;
        g_c0[idx] = 0.f;    g_c1[idx] = 0.f;
    }
}

// ---- skewed step: launch k does layer0(step k) and layer1(step k-1) ----
__global__ __launch_bounds__(NTHR, 1)
void step_kernel(const float* __restrict__ x,
                 const float* __restrict__ b0, const float* __restrict__ b1,
                 float* __restrict__ out, int k) {
    extern __shared__ char smc[];
    float2* Tall = (float2*)smc;
    float*  Wall = (float*)(smc + SM_T_BYTES);
    ull*    redA = (ull*)(smc + SM_T_BYTES + SM_W_BYTES);
    ull*    redB = redA + SM_RED_ULL;

    const int tid  = threadIdx.x;
    const int cta  = blockIdx.x;
    const int wrp  = tid >> 5;
    const int q    = wrp >> 1;         // K-quarter 0..3 (owns k [q*256, q*256+256))
    const int hl   = wrp & 1;          // col-group (uniform per warp)
    const int r    = tid & 31;         // row pair: r, r+32
    const int tid64 = tid & 63;
    const int barid = 1 + q;
    const int hcbase = cta * 4 + hl * 2;
    const int p = k & 1, pq = p ^ 1;

    float2* Tq = Tall + q * (3 * T_F2);
    float*  Wq = Wall + q * (3 * W_FL);
    const int ksrc_off = (q & 1) * 256;     // k offset inside the quarter's source

    ull aA[8], aB[8];

    // ---- phase A: layer 0, step k: [x_t, h0_prev] @ W0 ----
    if (k < S_LEN) {
#pragma unroll
        for (int j = 0; j < 8; j++) { aA[j] = 0ull; aB[j] = 0ull; }
        const float* src = ((q < 2) ? (x + (size_t)k * BATCH * HID) : g_h0[p]) + ksrc_off;
        const float* wsrc = g_wpack[0] + cta * 16384 + q * 4096;
        run_pipe(src, wsrc, Tq, Wq, tid64, r, hl, barid, aA, aB);
        if (q != 0) {
            ull* slot = redA + (size_t)((q - 1) * 64 + tid64) * RED_STRIDE;
#pragma unroll
            for (int j = 0; j < 8; j++) { slot[j] = aA[j]; slot[8 + j] = aB[j]; }
        }
    }
    __syncthreads();
    if (k < S_LEN && q == 0) {
        do_epilogue(aA, aB, redA, tid64, b0, g_h0[pq], g_c0, nullptr, r, r + 32, hcbase);
    }

    // ---- phase B: layer 1, step k-1: [h0_prev_launch, h1_prev] @ W1 ----
    if (k > 0) {
#pragma unroll
        for (int j = 0; j < 8; j++) { aA[j] = 0ull; aB[j] = 0ull; }
        const float* src = ((q < 2) ? g_h0[p] : g_h1[p]) + ksrc_off;
        const float* wsrc = g_wpack[1] + cta * 16384 + q * 4096;
        run_pipe(src, wsrc, Tq, Wq, tid64, r, hl, barid, aA, aB);
        if (q != 0) {
            ull* slot = redB + (size_t)((q - 1) * 64 + tid64) * RED_STRIDE;
#pragma unroll
            for (int j = 0; j < 8; j++) { slot[j] = aA[j]; slot[8 + j] = aB[j]; }
        }
    }
    __syncthreads();
    if (k > 0 && q == 0) {
        do_epilogue(aA, aB, redB, tid64, b1, g_h1[pq], g_c1,
                    out + (size_t)(k - 1) * BATCH * HID, r, r + 32, hcbase);
    }
}

extern "C" void kernel_launch(void* const* d_in, const int* in_sizes, int n_in,
                              void* d_out, int out_size) {
    const float* x   = (const float*)d_in[0];
    const float* Wx0 = (const float*)d_in[1];
    const float* Wh0 = (const float*)d_in[2];
    const float* b0  = (const float*)d_in[3];
    const float* Wx1 = (const float*)d_in[4];
    const float* Wh1 = (const float*)d_in[5];
    const float* b1  = (const float*)d_in[6];
    float* out = (float*)d_out;

    static int attr_done = 0;
    if (!attr_done) {
        cudaFuncSetAttribute(step_kernel,
                             cudaFuncAttributeMaxDynamicSharedMemorySize, SM_TOTAL);
        attr_done = 1;
    }

    pack_kernel<<<NCTA, 256>>>(Wx0, Wh0, Wx1, Wh1);
    init_kernel<<<(BATCH * HID + 255) / 256, 256>>>();
    for (int k = 0; k <= S_LEN; k++) {
        step_kernel<<<NCTA, NTHR, SM_TOTAL>>>(x, b0, b1, out, k);
    }
}

// round 8
// speedup vs baseline: 2.0782x; 1.3585x over previous
#include <cuda_runtime.h>
#include <cuda_bf16.h>
#include <cstdint>

#define SLEN  512
#define BATCH 64
#define HID   512
#define NCTA  128
#define NTHR  256
#define AB    272                 // smem row pitch bytes (136 bf16): conflict-free ldmatrix
#define A_BUF (128 * AB)          // 34816
#define B_BUF (32 * AB)           // 8704
#define SM_A  0                   // 2 x A_BUF
#define SM_B  (2 * A_BUF)         // 2 x B_BUF
#define SM_X  (SM_B + 2 * B_BUF)  // xchg: 64 x 17 floats
#define SM_TOTAL (SM_X + 64 * 17 * 4)

typedef __nv_bfloat16 bf16;

// ---- persistent device state (allocation-free rule) ----
__device__ __align__(128) bf16  gx[SLEN][128][HID];   // x split: rows 0-63 hi, 64-127 lo
__device__ __align__(128) bf16  gh0s[2][128][HID];    // h0 split, ping-pong
__device__ __align__(128) bf16  gh1s[2][128][HID];    // h1 split, ping-pong
__device__ __align__(128) float g_c0[BATCH * HID];
__device__ __align__(128) float g_c1[BATCH * HID];
// weights: [layer][cta][n'(32)][k(1024)]; n'<16 = hi of col(n'), n'>=16 = lo of col(n'-16)
// col(n) = g*512 + cta*4 + q, with g = (n&1)*2 + (n>>3), q = (n>>1)&3
__device__ __align__(128) bf16  g_wb[2][NCTA][32][1024];

// ---------------- helpers ----------------
__device__ __forceinline__ uint32_t smem_u32(const void* p) {
    uint32_t a;
    asm("{ .reg .u64 t; cvta.to.shared.u64 t, %1; cvt.u32.u64 %0, t; }" : "=r"(a) : "l"(p));
    return a;
}
__device__ __forceinline__ void cpa16(uint32_t dst, const void* src) {
    asm volatile("cp.async.cg.shared.global [%0], [%1], 16;\n" :: "r"(dst), "l"(src));
}
__device__ __forceinline__ void cp_commit() { asm volatile("cp.async.commit_group;\n" ::: "memory"); }
__device__ __forceinline__ void cp_wait1()  { asm volatile("cp.async.wait_group 1;\n" ::: "memory"); }
__device__ __forceinline__ void cp_wait0()  { asm volatile("cp.async.wait_group 0;\n" ::: "memory"); }

__device__ __forceinline__ void ldsm4(uint32_t& r0, uint32_t& r1, uint32_t& r2, uint32_t& r3,
                                      uint32_t addr) {
    asm volatile("ldmatrix.sync.aligned.m8n8.x4.shared.b16 {%0,%1,%2,%3}, [%4];"
                 : "=r"(r0), "=r"(r1), "=r"(r2), "=r"(r3) : "r"(addr));
}
__device__ __forceinline__ void mma16816(float* d, const uint32_t* a, uint32_t b0, uint32_t b1) {
    asm volatile(
        "mma.sync.aligned.m16n8k16.row.col.f32.bf16.bf16.f32 "
        "{%0,%1,%2,%3}, {%4,%5,%6,%7}, {%8,%9}, {%0,%1,%2,%3};"
        : "+f"(d[0]), "+f"(d[1]), "+f"(d[2]), "+f"(d[3])
        : "r"(a[0]), "r"(a[1]), "r"(a[2]), "r"(a[3]), "r"(b0), "r"(b1));
}
__device__ __forceinline__ float sigf(float x) { return 1.0f / (1.0f + __expf(-x)); }

// ---- stage one 128-k chunk: A[128 rows] + B[32 n'] into padded smem tiles ----
__device__ __forceinline__ void stage_chunk(uint32_t sb, int buf, int c,
                                            const bf16* __restrict__ srcX,
                                            const bf16* __restrict__ srcH,
                                            const bf16* __restrict__ wsrc, int tid) {
    const bf16* a = (c < 4) ? (srcX + c * 128) : (srcH + (c - 4) * 128);
    uint32_t ab = sb + SM_A + buf * A_BUF;
#pragma unroll
    for (int i = 0; i < 8; i++) {
        int u = i * NTHR + tid;            // 0..2047
        int row = u >> 4, cu = u & 15;
        cpa16(ab + row * AB + cu * 16, a + row * HID + cu * 8);
    }
    const bf16* b = wsrc + c * 128;
    uint32_t bb = sb + SM_B + buf * B_BUF;
#pragma unroll
    for (int i = 0; i < 2; i++) {
        int u = i * NTHR + tid;            // 0..511
        int row = u >> 4, cu = u & 15;
        cpa16(bb + row * AB + cu * 16, b + row * 1024 + cu * 8);
    }
}

// ---- compute one chunk: warp w owns rows 16w..16w+15, all 32 n' ----
__device__ __forceinline__ void mma_chunk(uint32_t sb, int buf, int w, int l, float* d) {
    uint32_t sA  = sb + SM_A + buf * A_BUF + (16 * w + (l & 15)) * AB + (l >> 4) * 16;
    uint32_t sB0 = sb + SM_B + buf * B_BUF + (l & 15) * AB + (l >> 4) * 16;
    uint32_t sB1 = sB0 + 16 * AB;
#pragma unroll
    for (int j = 0; j < 8; j++) {          // 8 k-steps of 16
        uint32_t a[4], p0, p1, p2, p3, q0, q1, q2, q3;
        ldsm4(a[0], a[1], a[2], a[3], sA + j * 32);
        ldsm4(p0, p1, p2, p3, sB0 + j * 32);   // n' 0-15 (hi cols)
        ldsm4(q0, q1, q2, q3, sB1 + j * 32);   // n' 16-31 (lo cols)
        mma16816(d + 0,  a, p0, p2);       // tile0: n 0-7
        mma16816(d + 4,  a, p1, p3);       // tile1: n 8-15
        mma16816(d + 8,  a, q0, q2);       // tile2: n 16-23
        mma16816(d + 12, a, q1, q3);       // tile3: n 24-31
    }
}

// ---- one gate-GEMM phase: D'[128 x 32] over K=1024, 8 chunks double-buffered ----
__device__ void gemm_phase(uint32_t sb, const bf16* __restrict__ srcX,
                           const bf16* __restrict__ srcH, const bf16* __restrict__ wsrc,
                           int tid, int w, int l, float* d) {
#pragma unroll
    for (int j = 0; j < 16; j++) d[j] = 0.f;
    stage_chunk(sb, 0, 0, srcX, srcH, wsrc, tid);
    cp_commit();
#pragma unroll 1
    for (int c = 0; c < 8; c++) {
        if (c < 7) {
            stage_chunk(sb, (c + 1) & 1, c + 1, srcX, srcH, wsrc, tid);
            cp_commit();
            cp_wait1();                    // chunk c landed
        } else {
            cp_wait0();
        }
        __syncthreads();                   // data visible to all warps
        mma_chunk(sb, c & 1, w, l, d);
        __syncthreads();                   // compute done before buffer reuse
    }
}

// ---- epilogue: fold cols (n,n+16) locally, rows (r,r+64) via smem, cell update ----
__device__ void epilogue(float* d, float* __restrict__ xchg,
                         const float* __restrict__ bias, float* __restrict__ cst,
                         bf16* __restrict__ hdst, float* __restrict__ odst,
                         int cta, int w, int l) {
    float ff[2][4];                        // [t][reg]: col-folded
#pragma unroll
    for (int t = 0; t < 2; t++)
#pragma unroll
        for (int r = 0; r < 4; r++) ff[t][r] = d[t * 4 + r] + d[(t + 2) * 4 + r];

    const int q = l & 3;
    const int row0 = 16 * w + (l >> 2);    // warp's first row; second = row0+8
    // gate of (t, j) = j*2 + t:  t0j0=f, t1j0=i1, t0j1=i2, t1j1=o
    if (w >= 4) {                          // rows 64-127: lo partials -> xchg
#pragma unroll
        for (int rr = 0; rr < 2; rr++) {
            int row = row0 + rr * 8 - 64;
#pragma unroll
            for (int t = 0; t < 2; t++)
#pragma unroll
                for (int j = 0; j < 2; j++)
                    xchg[row * 17 + (j * 2 + t) * 4 + q] = ff[t][rr * 2 + j];
        }
    }
    __syncthreads();
    if (w < 4) {                           // rows 0-63: full result
        const int hc = cta * 4 + q;
        float b2f = 2.f * bias[hc];
        float b2i1 = 2.f * bias[HID + hc];
        float b2i2 = 2.f * bias[2 * HID + hc];
        float b2o = 2.f * bias[3 * HID + hc];
#pragma unroll
        for (int rr = 0; rr < 2; rr++) {
            int row = row0 + rr * 8;
            const float* xr = xchg + row * 17;
            float gf = ff[0][rr * 2 + 0] + xr[0 * 4 + q] + b2f;
            float g1 = ff[1][rr * 2 + 0] + xr[1 * 4 + q] + b2i1;
            float g2 = ff[0][rr * 2 + 1] + xr[2 * 4 + q] + b2i2;
            float go = ff[1][rr * 2 + 1] + xr[3 * 4 + q] + b2o;
            float c = cst[row * HID + hc];
            c = sigf(gf) * c + sigf(g1) * tanhf(g2);
            cst[row * HID + hc] = c;
            float h = sigf(go) * tanhf(c);
            bf16 hi = __float2bfloat16(h);
            bf16 lo = __float2bfloat16(h - __bfloat162float(hi));
            hdst[row * HID + hc] = hi;
            hdst[(row + 64) * HID + hc] = lo;
            if (odst) odst[row * HID + hc] = h;
        }
    }
    __syncthreads();                       // xchg reuse safety across phases
}

// ---- one-time per replay: split x into bf16 hi/lo stacked rows ----
__global__ void pack_x(const float* __restrict__ x) {
    size_t i = (size_t)blockIdx.x * blockDim.x + threadIdx.x;
    if (i < (size_t)SLEN * BATCH * HID) {
        int kk = (int)(i % HID);
        size_t sr = i / HID;
        int r = (int)(sr % BATCH);
        int s = (int)(sr / BATCH);
        float v = x[i];
        bf16 hi = __float2bfloat16(v);
        gx[s][r][kk] = hi;
        gx[s][64 + r][kk] = __float2bfloat16(v - __bfloat162float(hi));
    }
}

// ---- one-time per replay: split + permute weights ----
__global__ void pack_w(const float* __restrict__ Wx0, const float* __restrict__ Wh0,
                       const float* __restrict__ Wx1, const float* __restrict__ Wh1) {
    size_t i = (size_t)blockIdx.x * blockDim.x + threadIdx.x;  // 2*128*32*1024
    if (i >= (size_t)2 * NCTA * 32 * 1024) return;
    int kk = (int)(i & 1023);
    size_t t = i >> 10;
    int n32 = (int)(t & 31); t >>= 5;
    int cta = (int)(t & 127);
    int layer = (int)(t >> 7);
    int n = n32 & 15;                      // real col index within CTA
    int g = (n & 1) * 2 + (n >> 3);        // gate permutation (thread-local gate sets)
    int q = (n >> 1) & 3;
    int col = g * HID + cta * 4 + q;
    const float* Wx = layer ? Wx1 : Wx0;
    const float* Wh = layer ? Wh1 : Wh0;
    float v = (kk < HID) ? Wx[kk * 2048 + col] : Wh[(kk - HID) * 2048 + col];
    bf16 hi = __float2bfloat16(v);
    g_wb[layer][cta][n32][kk] = (n32 < 16) ? hi
                              : __float2bfloat16(v - __bfloat162float(hi));
}

__global__ void init_kernel() {
    int idx = blockIdx.x * blockDim.x + threadIdx.x;
    if (idx < 2 * 128 * HID) {
        ((bf16*)gh0s)[idx] = __float2bfloat16(0.f);
        ((bf16*)gh1s)[idx] = __float2bfloat16(0.f);
    }
    if (idx < BATCH * HID) { g_c0[idx] = 0.f; g_c1[idx] = 0.f; }
}

// ---- skewed step: launch k does layer0(step k) then layer1(step k-1) ----
__global__ __launch_bounds__(NTHR, 1)
void step_kernel(const float* __restrict__ b0, const float* __restrict__ b1,
                 float* __restrict__ out, int k) {
    extern __shared__ char smem[];
    uint32_t sb = smem_u32(smem);
    float* xchg = (float*)(smem + SM_X);
    const int tid = threadIdx.x, w = tid >> 5, l = tid & 31;
    const int cta = blockIdx.x;
    const int p = k & 1, pq = p ^ 1;

    float d[16];

    // phase A: layer 0, step k: [x_k ; h0_prev] @ W0
    if (k < SLEN) {
        gemm_phase(sb, &gx[k][0][0], &gh0s[p][0][0], &g_wb[0][cta][0][0], tid, w, l, d);
        epilogue(d, xchg, b0, g_c0, &gh0s[pq][0][0], nullptr, cta, w, l);
    }

    // phase B: layer 1, step k-1: [h0(step k-1) ; h1_prev] @ W1
    if (k > 0) {
        gemm_phase(sb, &gh0s[p][0][0], &gh1s[p][0][0], &g_wb[1][cta][0][0], tid, w, l, d);
        epilogue(d, xchg, b1, g_c1, &gh1s[pq][0][0],
                 out + (size_t)(k - 1) * BATCH * HID, cta, w, l);
    }
}

extern "C" void kernel_launch(void* const* d_in, const int* in_sizes, int n_in,
                              void* d_out, int out_size) {
    const float* x   = (const float*)d_in[0];
    const float* Wx0 = (const float*)d_in[1];
    const float* Wh0 = (const float*)d_in[2];
    const float* b0  = (const float*)d_in[3];
    const float* Wx1 = (const float*)d_in[4];
    const float* Wh1 = (const float*)d_in[5];
    const float* b1  = (const float*)d_in[6];
    float* out = (float*)d_out;

    static int attr_done = 0;
    if (!attr_done) {
        cudaFuncSetAttribute(step_kernel,
                             cudaFuncAttributeMaxDynamicSharedMemorySize, SM_TOTAL);
        attr_done = 1;
    }

    pack_x<<<(SLEN * BATCH * HID + 255) / 256, 256>>>(x);
    pack_w<<<(2 * NCTA * 32 * 1024 + 255) / 256, 256>>>(Wx0, Wh0, Wx1, Wh1);
    init_kernel<<<(2 * 128 * HID + 255) / 256, 256>>>();
    for (int k = 0; k <= SLEN; k++) {
        step_kernel<<<NCTA, NTHR, SM_TOTAL>>>(b0, b1, out, k);
    }
}